// round 9
// baseline (speedup 1.0000x reference)
#include <cuda_runtime.h>
#include <cuda_fp16.h>

// Problem constants (from reference setup_inputs)
#define Bn 8
#define Hn 768
#define Wn 768
#define NPIX (Bn * Hn * Wn)          // 4,718,592
#define HWn (Hn * Wn)
#define PROP_TIME 24
#define GROUP 4                       // per-group working set ~66MB, L2-resident

#define FULLMASK 0xffffffffu

// 8 fp16 weights per pixel, one 16B vector load
struct __align__(16) W8 { __half2 h[4]; };

// Scratch: __device__ globals (allocation-free per harness rules).
__device__ W8    g_wh[NPIX];          // ~75.5 MB total, 37.7 MB per group
__device__ float g_base[NPIX];        // ~19 MB
__device__ float g_bufA[NPIX];        // ~19 MB
__device__ float g_bufB[NPIX];        // ~19 MB

// 8-neighbor offsets (dy, dx), reference order
__constant__ int c_dy[8] = {-5, -1, 0, 0, 5, 1,  0,  0};
__constant__ int c_dx[8] = { 0,  0, 5, 1, 0, 0, -5, -1};

// ---------------------------------------------------------------------------
// Precompute: normalized affinity weights (fp16-rounded), folded base from the
// ROUNDED weights. mask px: w=0, base=raw.  else: base = (1 - sum(w)) * raw.
// ---------------------------------------------------------------------------
__global__ void precompute_kernel(const float* __restrict__ guid,
                                  const float* __restrict__ blur,
                                  const float* __restrict__ sparse)
{
    int i = blockIdx.x * blockDim.x + threadIdx.x;
    if (i >= NPIX) return;

    int x = i % Wn;
    int t = i / Wn;
    int y = t % Hn;
    int b = t / Hn;

    const float* gb = guid + (size_t)b * 8 * HWn;

    float w[8];
    float s = 0.0f;
#pragma unroll
    for (int c = 0; c < 8; ++c) {
        int yy = y + c_dy[c];
        int xx = x + c_dx[c];
        float v = 0.0f;
        if ((unsigned)yy < (unsigned)Hn && (unsigned)xx < (unsigned)Wn)
            v = gb[(size_t)c * HWn + yy * Wn + xx];
        w[c] = v;
        s += fabsf(v);
    }
    float inv = 1.0f / fmaxf(s, 1e-6f);
#pragma unroll
    for (int c = 0; c < 8; ++c) w[c] *= inv;

    float raw  = blur[i];
    bool  mask = sparse[i] > 0.0f;

    if (mask) {
#pragma unroll
        for (int c = 0; c < 8; ++c) w[c] = 0.0f;
    }

    W8 pack;
    float gs = 0.0f;
#pragma unroll
    for (int c = 0; c < 4; ++c) {
        __half2 h = __floats2half2_rn(w[2 * c], w[2 * c + 1]);
        pack.h[c] = h;
        float2 back = __half22float2(h);
        gs += back.x + back.y;
    }

    g_wh[i]   = pack;
    g_base[i] = mask ? raw : (1.0f - gs) * raw;
}

// ---------------------------------------------------------------------------
// One propagation step, 1 px/thread, horizontal taps via warp shuffle.
// Warp covers 32 consecutive x. Center row value loaded once per lane;
// 10 halo values loaded by lanes 0-9. Taps x-5,x-1,x+1,x+5 composed with
// SHFL — removes 4 of the 8 tap loads per pixel (L1-access bound kernel).
// ---------------------------------------------------------------------------
__global__ void __launch_bounds__(512) prop_kernel(const float* __restrict__ rin,
                                                   float* __restrict__ rout,
                                                   int b0)
{
    const int lane = threadIdx.x;                 // 0..31
    const int x  = blockIdx.x * 32 + lane;
    const int y  = blockIdx.y * 16 + threadIdx.y;
    const int b  = b0 + blockIdx.z;

    const size_t boff = (size_t)b * HWn;
    const float* row = rin + boff + (size_t)y * Wn;
    const size_t i = boff + (size_t)y * Wn + x;

    // ---- horizontal window: center + 10-wide halo across the warp ----
    // window[k] = row value at X0-5+k, k=0..41  (X0 = x - lane)
    float c0 = __ldg(row + x);                    // window[lane+5]
    float hl = 0.0f;                              // lanes 0-4: window[lane]; lanes 5-9: window[lane+32]
    if (lane < 10) {
        int gxh = x - lane + ((lane < 5) ? (lane - 5) : (lane + 27));
        if ((unsigned)gxh < (unsigned)Wn) hl = __ldg(row + gxh);
    }

    float s_c_m5 = __shfl_sync(FULLMASK, c0, (lane - 5) & 31);
    float s_h_ln = __shfl_sync(FULLMASK, hl, lane & 31);
    float lf5 = (lane >= 5) ? s_c_m5 : s_h_ln;

    float s_c_m1 = __shfl_sync(FULLMASK, c0, (lane - 1) & 31);
    float s_h_4  = __shfl_sync(FULLMASK, hl, 4);
    float lf1 = (lane >= 1) ? s_c_m1 : s_h_4;

    float s_c_p1 = __shfl_sync(FULLMASK, c0, (lane + 1) & 31);
    float s_h_5  = __shfl_sync(FULLMASK, hl, 5);
    float rt1 = (lane < 31) ? s_c_p1 : s_h_5;

    float s_c_p5 = __shfl_sync(FULLMASK, c0, (lane + 5) & 31);
    float s_h_l22 = __shfl_sync(FULLMASK, hl, (lane - 22) & 31);
    float rt5 = (lane < 27) ? s_c_p5 : s_h_l22;

    // ---- vertical taps: L1-cached (reused across block rows) ----
    float up5 = (y >= 5)     ? __ldg(row - 5 * Wn + x) : 0.0f;
    float up1 = (y >= 1)     ? __ldg(row - Wn + x)     : 0.0f;
    float dn5 = (y + 5 < Hn) ? __ldg(row + 5 * Wn + x) : 0.0f;
    float dn1 = (y + 1 < Hn) ? __ldg(row + Wn + x)     : 0.0f;

    // ---- weights + base: L2-resident streams, skip L1 ----
    uint4 u = __ldcg(reinterpret_cast<const uint4*>(&g_wh[i]));
    float2 w01 = __half22float2(*reinterpret_cast<__half2*>(&u.x));
    float2 w23 = __half22float2(*reinterpret_cast<__half2*>(&u.y));
    float2 w45 = __half22float2(*reinterpret_cast<__half2*>(&u.z));
    float2 w67 = __half22float2(*reinterpret_cast<__half2*>(&u.w));
    float acc = __ldcg(&g_base[i]);

    acc = fmaf(w01.x, up5, acc);
    acc = fmaf(w01.y, up1, acc);
    acc = fmaf(w23.x, rt5, acc);
    acc = fmaf(w23.y, rt1, acc);
    acc = fmaf(w45.x, dn5, acc);
    acc = fmaf(w45.y, dn1, acc);
    acc = fmaf(w67.x, lf5, acc);
    acc = fmaf(w67.y, lf1, acc);

    __stcg(&rout[i], acc);
}

// ---------------------------------------------------------------------------
// Launch: precompute once; per 4-batch group run all 24 iterations
// back-to-back so that group's fp16 weights stay L2-resident (~66MB set).
// ---------------------------------------------------------------------------
extern "C" void kernel_launch(void* const* d_in, const int* in_sizes, int n_in,
                              void* d_out, int out_size)
{
    const float* guid   = (const float*)d_in[0];   // (B,8,H,W)
    const float* blur   = (const float*)d_in[1];   // (B,1,H,W)
    const float* sparse = (const float*)d_in[2];   // (B,1,H,W)
    float* out = (float*)d_out;                    // (B,1,H,W)

    float *bufA, *bufB;
    cudaGetSymbolAddress((void**)&bufA, g_bufA);
    cudaGetSymbolAddress((void**)&bufB, g_bufB);

    {
        const int threads = 256;
        const int blocks  = (NPIX + threads - 1) / threads;
        precompute_kernel<<<blocks, threads>>>(guid, blur, sparse);
    }

    dim3 blk(32, 16);                 // 512 threads, tile 32 x 16
    dim3 grd(Wn / 32, Hn / 16, GROUP);

    for (int g = 0; g < Bn / GROUP; ++g) {
        int b0 = g * GROUP;
        const float* cur = blur;
        for (int it = 0; it < PROP_TIME; ++it) {
            float* dst;
            if (it == PROP_TIME - 1)      dst = out;
            else if ((it & 1) == 0)       dst = bufA;
            else                          dst = bufB;
            prop_kernel<<<grd, blk>>>(cur, dst, b0);
            cur = dst;
        }
    }
}

// round 10
// speedup vs baseline: 1.1265x; 1.1265x over previous
#include <cuda_runtime.h>
#include <cuda_fp16.h>

// Problem constants (from reference setup_inputs)
#define Bn 8
#define Hn 768
#define Wn 768
#define NPIX (Bn * Hn * Wn)          // 4,718,592
#define HWn (Hn * Wn)
#define PROP_TIME 24
#define GROUP 4                       // per-group working set ~66MB, L2-resident

// 8 fp16 weights per pixel, one 16B vector load
struct __align__(16) W8 { __half2 h[4]; };

// Scratch: __device__ globals (allocation-free per harness rules).
__device__ W8    g_wh[NPIX];          // ~75.5 MB total, 37.7 MB per group
__device__ float g_base[NPIX];        // ~19 MB
__device__ float g_bufA[NPIX];        // ~19 MB
__device__ float g_bufB[NPIX];        // ~19 MB

// 8-neighbor offsets (dy, dx), reference order
__constant__ int c_dy[8] = {-5, -1, 0, 0, 5, 1,  0,  0};
__constant__ int c_dx[8] = { 0,  0, 5, 1, 0, 0, -5, -1};

// ---------------------------------------------------------------------------
// Precompute: normalized affinity weights (fp16-rounded), folded base from the
// ROUNDED weights. mask px: w=0, base=raw.  else: base = (1 - sum(w)) * raw.
// ---------------------------------------------------------------------------
__global__ void precompute_kernel(const float* __restrict__ guid,
                                  const float* __restrict__ blur,
                                  const float* __restrict__ sparse)
{
    int i = blockIdx.x * blockDim.x + threadIdx.x;
    if (i >= NPIX) return;

    int x = i % Wn;
    int t = i / Wn;
    int y = t % Hn;
    int b = t / Hn;

    const float* gb = guid + (size_t)b * 8 * HWn;

    float w[8];
    float s = 0.0f;
#pragma unroll
    for (int c = 0; c < 8; ++c) {
        int yy = y + c_dy[c];
        int xx = x + c_dx[c];
        float v = 0.0f;
        if ((unsigned)yy < (unsigned)Hn && (unsigned)xx < (unsigned)Wn)
            v = gb[(size_t)c * HWn + yy * Wn + xx];
        w[c] = v;
        s += fabsf(v);
    }
    float inv = 1.0f / fmaxf(s, 1e-6f);
#pragma unroll
    for (int c = 0; c < 8; ++c) w[c] *= inv;

    float raw  = blur[i];
    bool  mask = sparse[i] > 0.0f;   // sign() of a non-negative field

    if (mask) {
#pragma unroll
        for (int c = 0; c < 8; ++c) w[c] = 0.0f;
    }

    W8 pack;
    float gs = 0.0f;
#pragma unroll
    for (int c = 0; c < 4; ++c) {
        __half2 h = __floats2half2_rn(w[2 * c], w[2 * c + 1]);
        pack.h[c] = h;
        float2 back = __half22float2(h);
        gs += back.x + back.y;
    }

    g_wh[i]   = pack;
    g_base[i] = mask ? raw : (1.0f - gs) * raw;
}

// ---------------------------------------------------------------------------
// One propagation step: r_out = base + sum_c w_c * r_in[neighbor_c]
// 32x16 blocks. Weights/base via __ldcg (L2-resident stream, keep out of L1);
// r taps via __ldg (L1-cached: vertical taps reuse rows 2-4x within a block,
// horizontal taps reuse 128B lines ~4x). L1 has full 228KB (no smem).
// ---------------------------------------------------------------------------
__global__ void __launch_bounds__(512) prop_kernel(const float* __restrict__ rin,
                                                   float* __restrict__ rout,
                                                   int b0)
{
    int x = blockIdx.x * 32 + threadIdx.x;
    int y = blockIdx.y * 16 + threadIdx.y;
    int b = b0 + blockIdx.z;

    size_t i  = (size_t)b * HWn + (size_t)y * Wn + x;
    const float* rb = rin + (size_t)b * HWn;
    int yw = y * Wn;

    float up5 = (y >= 5)      ? __ldg(&rb[yw - 5 * Wn + x]) : 0.0f;
    float up1 = (y >= 1)      ? __ldg(&rb[yw - Wn + x])     : 0.0f;
    float rt5 = (x + 5 < Wn)  ? __ldg(&rb[yw + x + 5])      : 0.0f;
    float rt1 = (x + 1 < Wn)  ? __ldg(&rb[yw + x + 1])      : 0.0f;
    float dn5 = (y + 5 < Hn)  ? __ldg(&rb[yw + 5 * Wn + x]) : 0.0f;
    float dn1 = (y + 1 < Hn)  ? __ldg(&rb[yw + Wn + x])     : 0.0f;
    float lf5 = (x >= 5)      ? __ldg(&rb[yw + x - 5])      : 0.0f;
    float lf1 = (x >= 1)      ? __ldg(&rb[yw + x - 1])      : 0.0f;

    uint4 u = __ldcg(reinterpret_cast<const uint4*>(&g_wh[i]));
    float2 w01 = __half22float2(*reinterpret_cast<__half2*>(&u.x));
    float2 w23 = __half22float2(*reinterpret_cast<__half2*>(&u.y));
    float2 w45 = __half22float2(*reinterpret_cast<__half2*>(&u.z));
    float2 w67 = __half22float2(*reinterpret_cast<__half2*>(&u.w));

    float acc = __ldcg(&g_base[i]);
    acc = fmaf(w01.x, up5, acc);
    acc = fmaf(w01.y, up1, acc);
    acc = fmaf(w23.x, rt5, acc);
    acc = fmaf(w23.y, rt1, acc);
    acc = fmaf(w45.x, dn5, acc);
    acc = fmaf(w45.y, dn1, acc);
    acc = fmaf(w67.x, lf5, acc);
    acc = fmaf(w67.y, lf1, acc);

    __stcg(&rout[i], acc);
}

// ---------------------------------------------------------------------------
// Launch: precompute once; per 4-batch group run all 24 iterations
// back-to-back so that group's fp16 weights stay L2-resident (~66MB set).
// ---------------------------------------------------------------------------
extern "C" void kernel_launch(void* const* d_in, const int* in_sizes, int n_in,
                              void* d_out, int out_size)
{
    const float* guid   = (const float*)d_in[0];   // (B,8,H,W)
    const float* blur   = (const float*)d_in[1];   // (B,1,H,W)
    const float* sparse = (const float*)d_in[2];   // (B,1,H,W)
    float* out = (float*)d_out;                    // (B,1,H,W)

    float *bufA, *bufB;
    cudaGetSymbolAddress((void**)&bufA, g_bufA);
    cudaGetSymbolAddress((void**)&bufB, g_bufB);

    {
        const int threads = 256;
        const int blocks  = (NPIX + threads - 1) / threads;
        precompute_kernel<<<blocks, threads>>>(guid, blur, sparse);
    }

    dim3 blk(32, 16);
    dim3 grd(Wn / 32, Hn / 16, GROUP);

    for (int g = 0; g < Bn / GROUP; ++g) {
        int b0 = g * GROUP;
        const float* cur = blur;
        for (int it = 0; it < PROP_TIME; ++it) {
            float* dst;
            if (it == PROP_TIME - 1)      dst = out;
            else if ((it & 1) == 0)       dst = bufA;
            else                          dst = bufB;
            prop_kernel<<<grd, blk>>>(cur, dst, b0);
            cur = dst;
        }
    }
}